// round 2
// baseline (speedup 1.0000x reference)
#include <cuda_runtime.h>
#include <math.h>

// Scratch (static __device__ arrays -- no allocation at runtime)
__device__ float g_V[16 * 16];          // variational 16x16 orthogonal matrix, V[i][j]
__device__ float g_feats[4096 * 784];   // quanv features [B,784]
__device__ float g_h[4096 * 256];       // hidden layer  [B,256]

// ---------------------------------------------------------------------------
// Kernel 0: build V = (CNOT-ring * RY(d1)) * (CNOT-ring * RY(d0)) by applying
// the circuit to each of the 16 basis vectors. Trivial work; 1 thread.
// Wire w corresponds to bit (3-w) of the flattened state index.
// ---------------------------------------------------------------------------
__global__ void compute_V_kernel(const float* __restrict__ var_angles) {
    if (threadIdx.x != 0 || blockIdx.x != 0) return;
    for (int j = 0; j < 16; ++j) {
        float v[16];
        #pragma unroll
        for (int i = 0; i < 16; ++i) v[i] = (i == j) ? 1.0f : 0.0f;
        for (int d = 0; d < 2; ++d) {
            // RY(var[d][w]) on each wire
            for (int w = 0; w < 4; ++w) {
                float half = var_angles[d * 4 + w] * 0.5f;
                float c = cosf(half), s = sinf(half);
                int mask = 1 << (3 - w);
                for (int i = 0; i < 16; ++i) {
                    if (!(i & mask)) {
                        float v0 = v[i], v1 = v[i | mask];
                        v[i]        = c * v0 - s * v1;
                        v[i | mask] = s * v0 + c * v1;
                    }
                }
            }
            // CNOT ring: (0,1),(1,2),(2,3),(3,0)
            for (int cw = 0; cw < 4; ++cw) {
                int tw = (cw + 1) & 3;
                int cm = 1 << (3 - cw), tm = 1 << (3 - tw);
                for (int i = 0; i < 16; ++i) {
                    if ((i & cm) && !(i & tm)) {
                        float tmp = v[i]; v[i] = v[i | tm]; v[i | tm] = tmp;
                    }
                }
            }
        }
        for (int i = 0; i < 16; ++i) g_V[i * 16 + j] = v[i];
    }
}

// ---------------------------------------------------------------------------
// Kernel 1: quanvolution features. One block per image, one thread per patch.
// Encoder state is a tensor product of (cos(p/2), sin(p/2)); then t = V s and
// feat_w = sum_i sign_w(i) * t_i^2.
// ---------------------------------------------------------------------------
__global__ __launch_bounds__(256) void quanv_kernel(const float* __restrict__ x) {
    __shared__ __align__(16) float simg[784];
    __shared__ float sV[256];
    int b = blockIdx.x;
    int t = threadIdx.x;

    const float4* img4 = (const float4*)(x + (size_t)b * 784);
    if (t < 196) ((float4*)simg)[t] = img4[t];
    sV[t] = g_V[t];
    __syncthreads();

    if (t >= 196) return;
    int r = t / 14, c = t % 14;
    float p0 = simg[(2 * r) * 28 + 2 * c];
    float p1 = simg[(2 * r) * 28 + 2 * c + 1];
    float p2 = simg[(2 * r + 1) * 28 + 2 * c];
    float p3 = simg[(2 * r + 1) * 28 + 2 * c + 1];

    float s0, c0, s1, c1, s2, c2, s3, c3;
    sincosf(0.5f * p0, &s0, &c0);
    sincosf(0.5f * p1, &s1, &c1);
    sincosf(0.5f * p2, &s2, &c2);
    sincosf(0.5f * p3, &s3, &c3);

    float sv[16];
    #pragma unroll
    for (int i = 0; i < 16; ++i) {
        sv[i] = ((i & 8) ? s0 : c0) * ((i & 4) ? s1 : c1) *
                ((i & 2) ? s2 : c2) * ((i & 1) ? s3 : c3);
    }

    float f0 = 0.f, f1 = 0.f, f2 = 0.f, f3 = 0.f;
    #pragma unroll
    for (int i = 0; i < 16; ++i) {
        float ti = 0.f;
        #pragma unroll
        for (int j = 0; j < 16; ++j) ti += sV[i * 16 + j] * sv[j];
        float q = ti * ti;
        f0 += (i & 8) ? -q : q;
        f1 += (i & 4) ? -q : q;
        f2 += (i & 2) ? -q : q;
        f3 += (i & 1) ? -q : q;
    }
    float4 out4 = make_float4(f0, f1, f2, f3);
    ((float4*)(g_feats + (size_t)b * 784))[t] = out4;
}

// ---------------------------------------------------------------------------
// Kernel 2: H = relu(feats @ W1^T + b1).  M=B, N=256, K=784.
// BM=BN=64, BK=16, 256 threads, 4x4 micro-tiles.
// ---------------------------------------------------------------------------
#define BM 64
#define BN 64
#define BK 16

__global__ __launch_bounds__(256) void gemm1_relu_kernel(
    const float* __restrict__ W1,   // [256][784]
    const float* __restrict__ b1)   // [256]
{
    __shared__ __align__(16) float As[BK][68];   // padded to reduce STS conflicts
    __shared__ __align__(16) float Bs[BK][68];

    int bx = blockIdx.x;            // N tile (0..3)
    int by = blockIdx.y;            // M tile
    int t  = threadIdx.x;
    int tx = t & 15, ty = t >> 4;   // 16x16 thread grid
    int lrow = t >> 2;              // 0..63 : row within tile for global loads
    int lk4  = t & 3;               // 0..3  : float4 index along K

    const float* Aptr = g_feats + (size_t)(by * BM + lrow) * 784 + lk4 * 4;
    const float* Wptr = W1      + (size_t)(bx * BN + lrow) * 784 + lk4 * 4;

    float acc[4][4] = {};

    for (int kt = 0; kt < 784; kt += BK) {
        float4 a = *(const float4*)(Aptr + kt);
        float4 w = *(const float4*)(Wptr + kt);
        __syncthreads();
        As[lk4 * 4 + 0][lrow] = a.x; As[lk4 * 4 + 1][lrow] = a.y;
        As[lk4 * 4 + 2][lrow] = a.z; As[lk4 * 4 + 3][lrow] = a.w;
        Bs[lk4 * 4 + 0][lrow] = w.x; Bs[lk4 * 4 + 1][lrow] = w.y;
        Bs[lk4 * 4 + 2][lrow] = w.z; Bs[lk4 * 4 + 3][lrow] = w.w;
        __syncthreads();
        #pragma unroll
        for (int k = 0; k < BK; ++k) {
            float4 av = *(const float4*)&As[k][ty * 4];
            float4 bv = *(const float4*)&Bs[k][tx * 4];
            float aa[4] = {av.x, av.y, av.z, av.w};
            float bb[4] = {bv.x, bv.y, bv.z, bv.w};
            #pragma unroll
            for (int i = 0; i < 4; ++i)
                #pragma unroll
                for (int j = 0; j < 4; ++j)
                    acc[i][j] += aa[i] * bb[j];
        }
    }

    int m0 = by * BM + ty * 4;
    int n0 = bx * BN + tx * 4;
    float4 bias = *(const float4*)(b1 + n0);
    float bb4[4] = {bias.x, bias.y, bias.z, bias.w};
    #pragma unroll
    for (int i = 0; i < 4; ++i) {
        float4 o;
        o.x = fmaxf(acc[i][0] + bb4[0], 0.f);
        o.y = fmaxf(acc[i][1] + bb4[1], 0.f);
        o.z = fmaxf(acc[i][2] + bb4[2], 0.f);
        o.w = fmaxf(acc[i][3] + bb4[3], 0.f);
        *(float4*)(g_h + (size_t)(m0 + i) * 256 + n0) = o;
    }
}

// ---------------------------------------------------------------------------
// Kernel 3: logits = H @ W2^T + b2; log_softmax. One warp per row.
// ---------------------------------------------------------------------------
__global__ __launch_bounds__(256) void head_kernel(
    const float* __restrict__ W2,   // [10][256]
    const float* __restrict__ b2,   // [10]
    float* __restrict__ out)        // [B][10]
{
    __shared__ float sW[10 * 256];
    __shared__ float sb[10];
    int t = threadIdx.x;
    for (int i = t; i < 2560; i += 256) sW[i] = W2[i];
    if (t < 10) sb[t] = b2[t];
    __syncthreads();

    int warp = t >> 5, lane = t & 31;
    int m = blockIdx.x * 8 + warp;
    const float* hrow = g_h + (size_t)m * 256;

    float h8[8];
    #pragma unroll
    for (int i = 0; i < 8; ++i) h8[i] = hrow[lane + 32 * i];

    float logit[10];
    #pragma unroll
    for (int j = 0; j < 10; ++j) {
        float p = 0.f;
        #pragma unroll
        for (int i = 0; i < 8; ++i) p += h8[i] * sW[j * 256 + lane + 32 * i];
        #pragma unroll
        for (int o = 16; o > 0; o >>= 1) p += __shfl_xor_sync(0xffffffffu, p, o);
        logit[j] = p + sb[j];
    }

    if (lane == 0) {
        float mx = logit[0];
        #pragma unroll
        for (int j = 1; j < 10; ++j) mx = fmaxf(mx, logit[j]);
        float sum = 0.f;
        #pragma unroll
        for (int j = 0; j < 10; ++j) sum += expf(logit[j] - mx);
        float lse = mx + logf(sum);
        #pragma unroll
        for (int j = 0; j < 10; ++j) out[m * 10 + j] = logit[j] - lse;
    }
}

// ---------------------------------------------------------------------------
extern "C" void kernel_launch(void* const* d_in, const int* in_sizes, int n_in,
                              void* d_out, int out_size) {
    const float* x    = (const float*)d_in[0];   // [B,1,28,28]
    const float* var  = (const float*)d_in[1];   // [2,4]
    const float* W1   = (const float*)d_in[2];   // [256,784]
    const float* b1   = (const float*)d_in[3];   // [256]
    const float* W2   = (const float*)d_in[4];   // [10,256]
    const float* b2   = (const float*)d_in[5];   // [10]
    float* out = (float*)d_out;

    int B = in_sizes[0] / 784;                   // 4096

    compute_V_kernel<<<1, 1>>>(var);
    quanv_kernel<<<B, 256>>>(x);
    dim3 grid1(256 / BN, B / BM);
    gemm1_relu_kernel<<<grid1, 256>>>(W1, b1);
    head_kernel<<<B / 8, 256>>>(W2, b2, out);
}

// round 4
// speedup vs baseline: 1.9827x; 1.9827x over previous
#include <cuda_runtime.h>
#include <cuda_bf16.h>
#include <math.h>
#include <stdint.h>

#define KP 800               // 784 padded to multiple of 32
#define NB 4096              // batch

// Scratch (static __device__ arrays -- no runtime allocation)
__device__ float g_V[256];                      // 16x16 variational matrix
__device__ __nv_bfloat16 g_AH[NB * KP];         // feats hi  [B][KP]
__device__ __nv_bfloat16 g_AL[NB * KP];         // feats lo
__device__ __nv_bfloat16 g_WH[256 * KP];        // W1 hi    [256][KP]
__device__ __nv_bfloat16 g_WL[256 * KP];        // W1 lo
__device__ float g_h[NB * 256];                 // hidden   [B][256]

// ---------------------------------------------------------------------------
// Kernel 0: build V (16 threads, one basis column each)
// ---------------------------------------------------------------------------
__global__ void compute_V_kernel(const float* __restrict__ var_angles) {
    int j = threadIdx.x;
    if (j >= 16) return;
    float v[16];
    #pragma unroll
    for (int i = 0; i < 16; ++i) v[i] = (i == j) ? 1.0f : 0.0f;
    for (int d = 0; d < 2; ++d) {
        for (int w = 0; w < 4; ++w) {
            float half = var_angles[d * 4 + w] * 0.5f;
            float c = cosf(half), s = sinf(half);
            int mask = 1 << (3 - w);
            #pragma unroll
            for (int i = 0; i < 16; ++i) {
                if (!(i & mask)) {
                    float v0 = v[i], v1 = v[i | mask];
                    v[i]        = c * v0 - s * v1;
                    v[i | mask] = s * v0 + c * v1;
                }
            }
        }
        for (int cw = 0; cw < 4; ++cw) {
            int tw = (cw + 1) & 3;
            int cm = 1 << (3 - cw), tm = 1 << (3 - tw);
            #pragma unroll
            for (int i = 0; i < 16; ++i) {
                if ((i & cm) && !(i & tm)) {
                    float tmp = v[i]; v[i] = v[i | tm]; v[i | tm] = tmp;
                }
            }
        }
    }
    for (int i = 0; i < 16; ++i) g_V[i * 16 + j] = v[i];
}

// ---------------------------------------------------------------------------
// Kernel 1: quanvolution -> bf16 hi/lo features. One block/image, thread/patch.
// ---------------------------------------------------------------------------
__device__ __forceinline__ uint32_t pack_bf2(float a, float b) {
    uint32_t lo = (uint32_t)__bfloat16_as_ushort(__float2bfloat16(a));
    uint32_t hi = (uint32_t)__bfloat16_as_ushort(__float2bfloat16(b));
    return lo | (hi << 16);
}

__global__ __launch_bounds__(256) void quanv_kernel(const float* __restrict__ x) {
    __shared__ __align__(16) float simg[784];
    __shared__ float sV[256];
    int b = blockIdx.x;
    int t = threadIdx.x;

    const float4* img4 = (const float4*)(x + (size_t)b * 784);
    if (t < 196) ((float4*)simg)[t] = img4[t];
    sV[t] = g_V[t];
    __syncthreads();

    if (t < 196) {
        int r = t / 14, c = t % 14;
        float p0 = simg[(2 * r) * 28 + 2 * c];
        float p1 = simg[(2 * r) * 28 + 2 * c + 1];
        float p2 = simg[(2 * r + 1) * 28 + 2 * c];
        float p3 = simg[(2 * r + 1) * 28 + 2 * c + 1];

        float s0, c0, s1, c1, s2, c2, s3, c3;
        sincosf(0.5f * p0, &s0, &c0);
        sincosf(0.5f * p1, &s1, &c1);
        sincosf(0.5f * p2, &s2, &c2);
        sincosf(0.5f * p3, &s3, &c3);

        float sv[16];
        #pragma unroll
        for (int i = 0; i < 16; ++i) {
            sv[i] = ((i & 8) ? s0 : c0) * ((i & 4) ? s1 : c1) *
                    ((i & 2) ? s2 : c2) * ((i & 1) ? s3 : c3);
        }

        float f0 = 0.f, f1 = 0.f, f2 = 0.f, f3 = 0.f;
        #pragma unroll
        for (int i = 0; i < 16; ++i) {
            float ti = 0.f;
            #pragma unroll
            for (int j = 0; j < 16; ++j) ti += sV[i * 16 + j] * sv[j];
            float q = ti * ti;
            f0 += (i & 8) ? -q : q;
            f1 += (i & 4) ? -q : q;
            f2 += (i & 2) ? -q : q;
            f3 += (i & 1) ? -q : q;
        }
        // bf16 hi/lo split
        float h0 = __bfloat162float(__float2bfloat16(f0));
        float h1 = __bfloat162float(__float2bfloat16(f1));
        float h2 = __bfloat162float(__float2bfloat16(f2));
        float h3 = __bfloat162float(__float2bfloat16(f3));
        uint2 H = make_uint2(pack_bf2(f0, f1), pack_bf2(f2, f3));
        uint2 L = make_uint2(pack_bf2(f0 - h0, f1 - h1), pack_bf2(f2 - h2, f3 - h3));
        size_t base = (size_t)b * KP + 4 * t;
        *(uint2*)&g_AH[base] = H;
        *(uint2*)&g_AL[base] = L;
    } else if (t < 200) {
        // zero the K pad region [784, 800)
        uint2 z = make_uint2(0u, 0u);
        size_t base = (size_t)b * KP + 784 + 4 * (t - 196);
        *(uint2*)&g_AH[base] = z;
        *(uint2*)&g_AL[base] = z;
    }
}

// ---------------------------------------------------------------------------
// Kernel 1b: W1 -> bf16 hi/lo, K padded to 800 with zeros
// ---------------------------------------------------------------------------
__global__ __launch_bounds__(256) void convert_w1_kernel(const float* __restrict__ W1) {
    int n = blockIdx.x;
    for (int k = threadIdx.x; k < KP; k += 256) {
        float v = (k < 784) ? W1[n * 784 + k] : 0.f;
        __nv_bfloat16 h = __float2bfloat16(v);
        float lo = v - __bfloat162float(h);
        g_WH[(size_t)n * KP + k] = h;
        g_WL[(size_t)n * KP + k] = __float2bfloat16(lo);
    }
}

// ---------------------------------------------------------------------------
// Kernel 2: H = relu(A @ W1^T + b1) via bf16x3 tensor-core GEMM.
// M=4096, N=256, K=800(padded). BM=128, BN=64, BK=32, 256 thr (8 warps 4x2),
// warp tile 32x32, mma.m16n8k16, cp.async double buffered.
// Swizzle: 64B rows (4 x 16B chunks); chunk' = c ^ ((r>>1)&3) -> conflict-free
// for both the 4-chunk stores and ldmatrix 8-row phases.
// ---------------------------------------------------------------------------
#define STAGE_BYTES 24576
#define OFF_AH 0
#define OFF_AL 8192
#define OFF_WH 16384
#define OFF_WL 20480
#define NKT 25               // KP / 32

__device__ __forceinline__ void ldsm4(uint32_t* r, uint32_t a) {
    asm volatile("ldmatrix.sync.aligned.m8n8.x4.shared.b16 {%0,%1,%2,%3}, [%4];\n"
                 : "=r"(r[0]), "=r"(r[1]), "=r"(r[2]), "=r"(r[3]) : "r"(a));
}
__device__ __forceinline__ void mma16816(float* d, const uint32_t* a, uint32_t b0, uint32_t b1) {
    asm volatile(
        "mma.sync.aligned.m16n8k16.row.col.f32.bf16.bf16.f32 "
        "{%0,%1,%2,%3}, {%4,%5,%6,%7}, {%8,%9}, {%0,%1,%2,%3};\n"
        : "+f"(d[0]), "+f"(d[1]), "+f"(d[2]), "+f"(d[3])
        : "r"(a[0]), "r"(a[1]), "r"(a[2]), "r"(a[3]), "r"(b0), "r"(b1));
}
__device__ __forceinline__ void cp16(uint32_t dst, const void* src) {
    asm volatile("cp.async.cg.shared.global [%0], [%1], 16;\n" :: "r"(dst), "l"(src));
}

__global__ __launch_bounds__(256, 1) void gemm1_kernel(const float* __restrict__ b1) {
    __shared__ __align__(16) unsigned char smem[2 * STAGE_BYTES];
    uint32_t sbase = (uint32_t)__cvta_generic_to_shared(smem);
    int t = threadIdx.x;
    int bm = blockIdx.y, bn = blockIdx.x;
    int warp = t >> 5, lane = t & 31;
    int wm = warp >> 1, wn = warp & 1;

    // global-load indices (16B chunks)
    int ar = t >> 2;                 // A rows come in 2 halves (r, r+64)
    int ac = t & 3;
    uint32_t a_sw0 = (uint32_t)(ar * 64 + ((ac ^ ((ar >> 1) & 3)) << 4));
    int ar2 = ar + 64;
    uint32_t a_sw1 = (uint32_t)(ar2 * 64 + ((ac ^ ((ar2 >> 1) & 3)) << 4));
    const size_t a_goff0 = (size_t)(bm * 128 + ar) * KP + ac * 8;
    const size_t a_goff1 = (size_t)(bm * 128 + ar2) * KP + ac * 8;
    const size_t w_goff  = (size_t)(bn * 64 + ar) * KP + ac * 8;   // ar in 0..63
    uint32_t w_sw = a_sw0;

    float acc[2][4][4];
    #pragma unroll
    for (int mi = 0; mi < 2; ++mi)
        #pragma unroll
        for (int nj = 0; nj < 4; ++nj)
            #pragma unroll
            for (int e = 0; e < 4; ++e) acc[mi][nj][e] = 0.f;

    // prologue: stage 0
    {
        uint32_t B = sbase;
        cp16(B + OFF_AH + a_sw0, g_AH + a_goff0);
        cp16(B + OFF_AH + a_sw1, g_AH + a_goff1);
        cp16(B + OFF_AL + a_sw0, g_AL + a_goff0);
        cp16(B + OFF_AL + a_sw1, g_AL + a_goff1);
        cp16(B + OFF_WH + w_sw, g_WH + w_goff);
        cp16(B + OFF_WL + w_sw, g_WL + w_goff);
        asm volatile("cp.async.commit_group;\n");
    }

    for (int kt = 0; kt < NKT; ++kt) {
        if (kt + 1 < NKT) {
            int k0 = (kt + 1) * 32;
            uint32_t B = sbase + ((kt + 1) & 1) * STAGE_BYTES;
            cp16(B + OFF_AH + a_sw0, g_AH + a_goff0 + k0);
            cp16(B + OFF_AH + a_sw1, g_AH + a_goff1 + k0);
            cp16(B + OFF_AL + a_sw0, g_AL + a_goff0 + k0);
            cp16(B + OFF_AL + a_sw1, g_AL + a_goff1 + k0);
            cp16(B + OFF_WH + w_sw, g_WH + w_goff + k0);
            cp16(B + OFF_WL + w_sw, g_WL + w_goff + k0);
            asm volatile("cp.async.commit_group;\n");
            asm volatile("cp.async.wait_group 1;\n");
        } else {
            asm volatile("cp.async.wait_group 0;\n");
        }
        __syncthreads();

        uint32_t B = sbase + (kt & 1) * STAGE_BYTES;
        int grp = lane >> 3, li = lane & 7;
        #pragma unroll
        for (int ks = 0; ks < 2; ++ks) {
            int ko = ks * 16;
            uint32_t ah[2][4], al[2][4], bh[2][4], bl[2][4];
            // A fragments: groups -> (m0-7,k0)(m8-15,k0)(m0-7,k8)(m8-15,k8)
            int ra_l = li + ((grp & 1) << 3);
            int kea  = ko + ((grp >> 1) << 3);
            #pragma unroll
            for (int mi = 0; mi < 2; ++mi) {
                int r = wm * 32 + mi * 16 + ra_l;
                uint32_t off = (uint32_t)(r * 64 + (((kea >> 3) ^ ((r >> 1) & 3)) << 4));
                ldsm4(ah[mi], B + OFF_AH + off);
                ldsm4(al[mi], B + OFF_AL + off);
            }
            // B fragments: groups -> (n0-7,k0)(n0-7,k8)(n8-15,k0)(n8-15,k8)
            int rb_l = li + ((grp >> 1) << 3);
            int keb  = ko + ((grp & 1) << 3);
            #pragma unroll
            for (int nt = 0; nt < 2; ++nt) {
                int r = wn * 32 + nt * 16 + rb_l;
                uint32_t off = (uint32_t)(r * 64 + (((keb >> 3) ^ ((r >> 1) & 3)) << 4));
                ldsm4(bh[nt], B + OFF_WH + off);
                ldsm4(bl[nt], B + OFF_WL + off);
            }
            #pragma unroll
            for (int mi = 0; mi < 2; ++mi) {
                #pragma unroll
                for (int nj = 0; nj < 4; ++nj) {
                    int nt = nj >> 1, hf = nj & 1;
                    mma16816(acc[mi][nj], ah[mi], bh[nt][hf * 2], bh[nt][hf * 2 + 1]);
                    mma16816(acc[mi][nj], ah[mi], bl[nt][hf * 2], bl[nt][hf * 2 + 1]);
                    mma16816(acc[mi][nj], al[mi], bh[nt][hf * 2], bh[nt][hf * 2 + 1]);
                }
            }
        }
        __syncthreads();
    }

    // epilogue: bias + relu -> g_h
    int mrow = bm * 128 + wm * 32 + (lane >> 2);
    int ncol0 = bn * 64 + wn * 32 + (lane & 3) * 2;
    #pragma unroll
    for (int nj = 0; nj < 4; ++nj) {
        int col = ncol0 + nj * 8;
        float bb0 = __ldg(b1 + col), bb1 = __ldg(b1 + col + 1);
        #pragma unroll
        for (int mi = 0; mi < 2; ++mi) {
            int r0 = mrow + mi * 16;
            float2 v0 = make_float2(fmaxf(acc[mi][nj][0] + bb0, 0.f),
                                    fmaxf(acc[mi][nj][1] + bb1, 0.f));
            float2 v1 = make_float2(fmaxf(acc[mi][nj][2] + bb0, 0.f),
                                    fmaxf(acc[mi][nj][3] + bb1, 0.f));
            *(float2*)&g_h[(size_t)r0 * 256 + col] = v0;
            *(float2*)&g_h[(size_t)(r0 + 8) * 256 + col] = v1;
        }
    }
}

// ---------------------------------------------------------------------------
// Kernel 3: logits + log_softmax. 32 rows/block, warp/row, no lane-0 serialization.
// ---------------------------------------------------------------------------
__global__ __launch_bounds__(1024) void head_kernel(
    const float* __restrict__ W2, const float* __restrict__ b2,
    float* __restrict__ out) {
    __shared__ float sW[2560];
    __shared__ float sb[10];
    int t = threadIdx.x;
    for (int i = t; i < 2560; i += 1024) sW[i] = W2[i];
    if (t < 10) sb[t] = b2[t];
    __syncthreads();

    int warp = t >> 5, lane = t & 31;
    int m = blockIdx.x * 32 + warp;
    const float* hr = g_h + (size_t)m * 256;

    float h8[8];
    #pragma unroll
    for (int i = 0; i < 8; ++i) h8[i] = hr[lane + 32 * i];

    float p[10];
    #pragma unroll
    for (int j = 0; j < 10; ++j) {
        float s = 0.f;
        #pragma unroll
        for (int i = 0; i < 8; ++i) s += h8[i] * sW[j * 256 + lane + 32 * i];
        p[j] = s;
    }
    #pragma unroll
    for (int o = 16; o > 0; o >>= 1)
        #pragma unroll
        for (int j = 0; j < 10; ++j) p[j] += __shfl_xor_sync(0xffffffffu, p[j], o);
    #pragma unroll
    for (int j = 0; j < 10; ++j) p[j] += sb[j];

    float mx = p[0];
    #pragma unroll
    for (int j = 1; j < 10; ++j) mx = fmaxf(mx, p[j]);
    float sum = 0.f;
    #pragma unroll
    for (int j = 0; j < 10; ++j) sum += expf(p[j] - mx);
    float lse = mx + logf(sum);

    if (lane < 10) {
        float v;
        switch (lane) {
            case 0: v = p[0]; break; case 1: v = p[1]; break;
            case 2: v = p[2]; break; case 3: v = p[3]; break;
            case 4: v = p[4]; break; case 5: v = p[5]; break;
            case 6: v = p[6]; break; case 7: v = p[7]; break;
            case 8: v = p[8]; break; default: v = p[9]; break;
        }
        out[m * 10 + lane] = v - lse;
    }
}

// ---------------------------------------------------------------------------
extern "C" void kernel_launch(void* const* d_in, const int* in_sizes, int n_in,
                              void* d_out, int out_size) {
    const float* x   = (const float*)d_in[0];   // [B,1,28,28]
    const float* var = (const float*)d_in[1];   // [2,4]
    const float* W1  = (const float*)d_in[2];   // [256,784]
    const float* b1  = (const float*)d_in[3];   // [256]
    const float* W2  = (const float*)d_in[4];   // [10,256]
    const float* b2  = (const float*)d_in[5];   // [10]
    float* out = (float*)d_out;

    int B = in_sizes[0] / 784;                  // 4096

    compute_V_kernel<<<1, 16>>>(var);
    convert_w1_kernel<<<256, 256>>>(W1);
    quanv_kernel<<<B, 256>>>(x);
    dim3 grid1(256 / 64, B / 128);
    gemm1_kernel<<<grid1, 256>>>(b1);
    head_kernel<<<B / 32, 1024>>>(W2, b2, out);
}